// round 6
// baseline (speedup 1.0000x reference)
#include <cuda_runtime.h>
#include <cuda_bf16.h>
#include <math.h>

#define N0 2048
#define NPAD 4096
#define NBLOCKS 148         // 1 block/SM, all co-resident
#define NT 256              // 8 warps
#define NPHASES 100         // 50 iterations x 2 half-steps

// log2(e)/EPS  (EPS = 0.05)
#define KCONST 28.853900817779268f
// 1/4096
#define AMASS 0.000244140625f
#define SCALE 4096.0f

// ---- device state (allocations forbidden; static globals) ----
__device__ float g_y[N0];            // e^{u/eps}
__device__ float g_z[N0];            // e^{v/eps}
__device__ float g_ypad, g_zpad;
__device__ __align__(128) unsigned int g_ctr;    // barrier arrival counter
__device__ __align__(128) unsigned int g_flag;   // barrier release flag (own line)
__device__ float         g_E  [(size_t)N0 * N0];  // exp2(-K*C) fp32 (final)  16MB
__device__ __nv_bfloat16 g_Eb [(size_t)N0 * N0];  // bf16 kernel (iters)       8MB
__device__ __nv_bfloat16 g_Etb[(size_t)N0 * N0];  // bf16 kernel transposed    8MB

__device__ __forceinline__ float ex2(float x) {
    float y; asm("ex2.approx.ftz.f32 %0, %1;" : "=f"(y) : "f"(x)); return y;
}
__device__ __forceinline__ float rcp(float x) {
    float y; asm("rcp.approx.ftz.f32 %0, %1;" : "=f"(y) : "f"(x)); return y;
}
__device__ __forceinline__ float warpRedSum(float v) {
#pragma unroll
    for (int o = 16; o > 0; o >>= 1) v += __shfl_down_sync(0xffffffffu, v, o);
    return v;
}
__device__ __forceinline__ unsigned int ldacq(const unsigned int* p) {
    unsigned int v;
    asm volatile("ld.acquire.gpu.global.u32 %0, [%1];" : "=r"(v) : "l"(p));
    return v;
}
// unpack bf16x2 word -> two fp32 (2 ALU ops, no cvt)
__device__ __forceinline__ float2 b2f(unsigned int r) {
    float2 f;
    f.x = __uint_as_float(r << 16);
    f.y = __uint_as_float(r & 0xffff0000u);
    return f;
}

// ---- prep: E = exp2(-K*C) (fp32), Eb = bf16(E), Etb = bf16(E^T) ----
__global__ void prep_kernel(const float* __restrict__ in) {
    __shared__ float tile[32][33];
    int x = blockIdx.x * 32 + threadIdx.x;
    int y0 = blockIdx.y * 32 + threadIdx.y;
#pragma unroll
    for (int k = 0; k < 32; k += 8) {
        float c = in[(size_t)(y0 + k) * N0 + x];
        float e = ex2(-KCONST * c);
        g_E [(size_t)(y0 + k) * N0 + x] = e;
        g_Eb[(size_t)(y0 + k) * N0 + x] = __float2bfloat16(e);
        tile[threadIdx.y + k][threadIdx.x] = e;
    }
    __syncthreads();
    int x2 = blockIdx.y * 32 + threadIdx.x;
    int y2 = blockIdx.x * 32 + threadIdx.y;
#pragma unroll
    for (int k = 0; k < 32; k += 8)
        g_Etb[(size_t)(y2 + k) * N0 + x2] = __float2bfloat16(tile[threadIdx.x][threadIdx.y + k]);
}

// ---- initial state: v = 0 -> z = 1, z_pad = 1; barrier reset (replay-safe) ----
__global__ void init_kernel() {
    for (int j = threadIdx.x; j < N0; j += blockDim.x) g_z[j] = 1.0f;
    if (threadIdx.x == 0) {
        g_zpad = 1.0f;
        g_ctr = 0u;
        g_flag = 0u;
    }
}

// Persistent kernel, primal (mass) domain, bf16 kernel matrices, L1-resident.
// Block 0: 12 rows (6 warps) + pad warp  -> balanced vs other blocks' 13-14
// rows, so no per-phase straggler. Release: per-warp acquire-spin on the flag,
// then that warp immediately stages its zs slice.
__global__ void __launch_bounds__(NT, 1) sinkhorn_persistent() {
    const int tid = threadIdx.x;
    const int warp = tid >> 5, lane = tid & 31;
    const int b = blockIdx.x;

    int start, cnt;
    if (b == 0) { start = 0; cnt = 12; }
    else {
        start = 12 + (2036 * (b - 1)) / 147;
        cnt = 12 + (2036 * b) / 147 - start;     // 13 or 14
    }
    const int r0 = start + 2 * warp;
    const bool active = (warp < 7) && (2 * warp < cnt);
    const bool doR1 = (2 * warp + 1 < cnt);
    const bool doPad = (b == 0 && warp == 7);

    __shared__ float zs[N0];
    unsigned int phnum = 0;

    for (int ph = 0; ph < NPHASES; ++ph) {
        const int odd = ph & 1;
        const __nv_bfloat16* __restrict__ M = odd ? g_Etb : g_Eb;
        const float* xin = odd ? g_y : g_z;
        float* xout = odd ? g_z : g_y;

        // ---- wait for release (skip on phase 0: init already published) ----
        if (ph) {
            if (lane == 0) while (ldacq(&g_flag) < phnum) {}
            __syncwarp();
        }

        const float xpad_in = __ldcg(odd ? &g_ypad : &g_zpad);
        const float padterm = 2048.0f * xpad_in;

        // stage input masses: each warp loads its own 1/8 slice (2 float4/lane)
        {
            const float4* x4 = (const float4*)xin;
            int i0 = warp * 64 + lane;
            float4 t0 = __ldcg(x4 + i0);
            float4 t1 = __ldcg(x4 + i0 + 32);
            ((float4*)zs)[i0] = t0;
            ((float4*)zs)[i0 + 32] = t1;
        }
        __syncthreads();

        const float4* z4 = (const float4*)zs;
        if (active) {
            const uint4* e0 = (const uint4*)(M + (size_t)r0 * N0);
            const uint4* e1 = (const uint4*)(M + (size_t)(r0 + 1) * N0);
            float s0a = 0.f, s0b = 0.f, s1a = 0.f, s1b = 0.f;
#pragma unroll
            for (int k = 0; k < 8; ++k) {
                const int idx = lane + k * 32;           // uint4 = 8 bf16
                uint4 A = __ldg(e0 + idx);
                uint4 B = __ldg(e1 + idx);
                float4 za = z4[2 * idx];
                float4 zb = z4[2 * idx + 1];
                float2 a0 = b2f(A.x), a1 = b2f(A.y), a2 = b2f(A.z), a3 = b2f(A.w);
                s0a = fmaf(a0.x, za.x, s0a); s0b = fmaf(a0.y, za.y, s0b);
                s0a = fmaf(a1.x, za.z, s0a); s0b = fmaf(a1.y, za.w, s0b);
                s0a = fmaf(a2.x, zb.x, s0a); s0b = fmaf(a2.y, zb.y, s0b);
                s0a = fmaf(a3.x, zb.z, s0a); s0b = fmaf(a3.y, zb.w, s0b);
                float2 c0 = b2f(B.x), c1 = b2f(B.y), c2 = b2f(B.z), c3 = b2f(B.w);
                s1a = fmaf(c0.x, za.x, s1a); s1b = fmaf(c0.y, za.y, s1b);
                s1a = fmaf(c1.x, za.z, s1a); s1b = fmaf(c1.y, za.w, s1b);
                s1a = fmaf(c2.x, zb.x, s1a); s1b = fmaf(c2.y, zb.y, s1b);
                s1a = fmaf(c3.x, zb.z, s1a); s1b = fmaf(c3.y, zb.w, s1b);
            }
            float s0 = warpRedSum(s0a + s0b);
            float s1 = warpRedSum(s1a + s1b);
            if (lane == 0) {
                __stcg(&xout[r0], AMASS * rcp(s0 + padterm));
                if (doR1) __stcg(&xout[r0 + 1], AMASS * rcp(s1 + padterm));
            }
        } else if (doPad) {
            float sa = 0.f, sb = 0.f;
#pragma unroll
            for (int k = 0; k < 16; ++k) {
                float4 z = z4[lane + k * 32];
                sa += z.x + z.y; sb += z.z + z.w;
            }
            float s = warpRedSum(sa + sb);
            if (lane == 0) __stcg(odd ? &g_zpad : &g_ypad, AMASS * rcp(s + padterm));
        }

        // ---- barrier arrival ----
        ++phnum;
        __syncthreads();                       // all warps done with zs
        if (tid == 0) {
            __threadfence();                   // publish xout/pad writes
            unsigned int t = atomicAdd(&g_ctr, 1u) + 1u;
            if (t == NBLOCKS * phnum) {
                __threadfence();
                atomicExch(&g_flag, phnum);    // release
            }
        }
        // waiting happens at the top of the next phase (per-warp acquire spin)
    }
}

// ---- out = 4096 * min(1, y_i * z_j * E_ij) over padded 4096x4096 ----
// Columns >= 2048 are pad: e=1, z=z_pad -> constant per row. Each thread
// emits one computed float4 (left half) + one constant float4 (right half).
__global__ void __launch_bounds__(256) final_kernel(float* __restrict__ out) {
    int i = blockIdx.y;                                  // 0..4095
    int j4 = blockIdx.x * blockDim.x + threadIdx.x;      // 0..511 (left half)

    float zpad = g_zpad;
    float4 o, opad;
    if (i < N0) {
        float y = g_y[i];
        float4 z4 = ((const float4*)g_z)[j4];
        float4 e4 = ((const float4*)g_E)[(size_t)i * (N0 / 4) + j4];
        o.x = SCALE * fminf(1.0f, y * z4.x * e4.x);
        o.y = SCALE * fminf(1.0f, y * z4.y * e4.y);
        o.z = SCALE * fminf(1.0f, y * z4.z * e4.z);
        o.w = SCALE * fminf(1.0f, y * z4.w * e4.w);
        float pv = SCALE * fminf(1.0f, y * zpad);
        opad = make_float4(pv, pv, pv, pv);
    } else {
        float yp = g_ypad;
        float4 z4 = ((const float4*)g_z)[j4];
        o.x = SCALE * fminf(1.0f, yp * z4.x);
        o.y = SCALE * fminf(1.0f, yp * z4.y);
        o.z = SCALE * fminf(1.0f, yp * z4.z);
        o.w = SCALE * fminf(1.0f, yp * z4.w);
        float pv = SCALE * fminf(1.0f, yp * zpad);
        opad = make_float4(pv, pv, pv, pv);
    }
    float4* orow = (float4*)out + (size_t)i * (NPAD / 4);
    __stcs(orow + j4, o);
    __stcs(orow + j4 + 512, opad);
}

extern "C" void kernel_launch(void* const* d_in, const int* in_sizes, int n_in,
                              void* d_out, int out_size) {
    const float* C = (const float*)d_in[0];
    float* out = (float*)d_out;

    prep_kernel<<<dim3(N0 / 32, N0 / 32), dim3(32, 8)>>>(C);
    init_kernel<<<1, 256>>>();
    sinkhorn_persistent<<<NBLOCKS, NT>>>();
    final_kernel<<<dim3(2, NPAD), 256>>>(out);
}

// round 7
// speedup vs baseline: 1.3031x; 1.3031x over previous
#include <cuda_runtime.h>
#include <cuda_bf16.h>
#include <math.h>

#define N0 2048
#define NPAD 4096
#define NBLOCKS 148         // 1 block/SM, all co-resident
#define NT 256              // 8 warps
#define NPHASES 100         // 50 iterations x 2 half-steps

// log2(e)/EPS  (EPS = 0.05)
#define KCONST 28.853900817779268f
// 1/4096
#define AMASS 0.000244140625f
#define SCALE 4096.0f

// ---- device state (allocations forbidden; static globals) ----
__device__ float g_y[N0];            // e^{u/eps}
__device__ float g_z[N0];            // e^{v/eps}
__device__ float g_ypad, g_zpad;
__device__ __align__(128) unsigned int g_ctr;    // barrier arrival counter
__device__ __align__(128) unsigned int g_flag;   // barrier release flag (own line)
__device__ float         g_E  [(size_t)N0 * N0];  // exp2(-K*C) fp32 (final)  16MB
__device__ __nv_bfloat16 g_Eb [(size_t)N0 * N0];  // bf16 kernel (iters)       8MB
__device__ __nv_bfloat16 g_Etb[(size_t)N0 * N0];  // bf16 kernel transposed    8MB

__device__ __forceinline__ float ex2(float x) {
    float y; asm("ex2.approx.ftz.f32 %0, %1;" : "=f"(y) : "f"(x)); return y;
}
__device__ __forceinline__ float rcp(float x) {
    float y; asm("rcp.approx.ftz.f32 %0, %1;" : "=f"(y) : "f"(x)); return y;
}
__device__ __forceinline__ float warpRedSum(float v) {
#pragma unroll
    for (int o = 16; o > 0; o >>= 1) v += __shfl_down_sync(0xffffffffu, v, o);
    return v;
}
// unpack bf16x2 word -> two fp32 (2 ALU ops, no cvt)
__device__ __forceinline__ float2 b2f(unsigned int r) {
    float2 f;
    f.x = __uint_as_float(r << 16);
    f.y = __uint_as_float(r & 0xffff0000u);
    return f;
}

// ---- prep: E = exp2(-K*C) (fp32), Eb = bf16(E), Etb = bf16(E^T) ----
__global__ void prep_kernel(const float* __restrict__ in) {
    __shared__ float tile[32][33];
    int x = blockIdx.x * 32 + threadIdx.x;
    int y0 = blockIdx.y * 32 + threadIdx.y;
#pragma unroll
    for (int k = 0; k < 32; k += 8) {
        float c = in[(size_t)(y0 + k) * N0 + x];
        float e = ex2(-KCONST * c);
        g_E [(size_t)(y0 + k) * N0 + x] = e;
        g_Eb[(size_t)(y0 + k) * N0 + x] = __float2bfloat16(e);
        tile[threadIdx.y + k][threadIdx.x] = e;
    }
    __syncthreads();
    int x2 = blockIdx.y * 32 + threadIdx.x;
    int y2 = blockIdx.x * 32 + threadIdx.y;
#pragma unroll
    for (int k = 0; k < 32; k += 8)
        g_Etb[(size_t)(y2 + k) * N0 + x2] = __float2bfloat16(tile[threadIdx.x][threadIdx.y + k]);
}

// ---- initial state: v = 0 -> z = 1, z_pad = 1; barrier reset (replay-safe) ----
__global__ void init_kernel() {
    for (int j = threadIdx.x; j < N0; j += blockDim.x) g_z[j] = 1.0f;
    if (threadIdx.x == 0) {
        g_zpad = 1.0f;
        g_ctr = 0u;
        g_flag = 0u;
    }
}

// Persistent kernel, primal (mass) domain, bf16 kernel matrices, L1-resident.
//
// phase even: y_i = AMASS * rcp( sum_j Eb_ij  * z_j + 2048*z_pad )
// phase odd : z_j = AMASS * rcp( sum_i Etb_ji * y_i + 2048*y_pad )
// pad       : x_pad = AMASS * rcp( sum_j in_j + 2048*in_pad )
//
// Block 0: 12 rows (6 row-warps) + pad warp; blocks 1..147: 13-14 rows
// -> no straggler block. Barrier: single arrival + single .cg spinner per
// block (148 pollers total — measured fastest; per-warp acquire spinners
// regressed 25% in R6).
__global__ void __launch_bounds__(NT, 1) sinkhorn_persistent() {
    const int tid = threadIdx.x;
    const int warp = tid >> 5, lane = tid & 31;
    const int b = blockIdx.x;

    int start, cnt;
    if (b == 0) { start = 0; cnt = 12; }
    else {
        start = 12 + (2036 * (b - 1)) / 147;
        cnt = 12 + (2036 * b) / 147 - start;     // 13 or 14
    }
    const int r0 = start + 2 * warp;
    const bool active = (warp < 7) && (2 * warp < cnt);
    const bool doR1 = (2 * warp + 1 < cnt);
    const bool doPad = (b == 0 && warp == 7);

    __shared__ float zs[N0];
    unsigned int phnum = 0;

    for (int ph = 0; ph < NPHASES; ++ph) {
        const int odd = ph & 1;
        const __nv_bfloat16* __restrict__ M = odd ? g_Etb : g_Eb;
        const float* xin = odd ? g_y : g_z;
        float* xout = odd ? g_z : g_y;

        const float xpad_in = __ldcg(odd ? &g_ypad : &g_zpad);
        const float padterm = 2048.0f * xpad_in;

        // stage input masses: each warp loads its own 1/8 slice (2 float4/lane)
        {
            const float4* x4 = (const float4*)xin;
            int i0 = warp * 64 + lane;
            float4 t0 = __ldcg(x4 + i0);
            float4 t1 = __ldcg(x4 + i0 + 32);
            ((float4*)zs)[i0] = t0;
            ((float4*)zs)[i0 + 32] = t1;
        }
        __syncthreads();

        const float4* z4 = (const float4*)zs;
        if (active) {
            const uint4* e0 = (const uint4*)(M + (size_t)r0 * N0);
            const uint4* e1 = (const uint4*)(M + (size_t)(r0 + 1) * N0);
            float s0a = 0.f, s0b = 0.f, s1a = 0.f, s1b = 0.f;
#pragma unroll
            for (int k = 0; k < 8; ++k) {
                const int idx = lane + k * 32;           // uint4 = 8 bf16
                uint4 A = __ldg(e0 + idx);
                uint4 B = __ldg(e1 + idx);
                float4 za = z4[2 * idx];
                float4 zb = z4[2 * idx + 1];
                float2 a0 = b2f(A.x), a1 = b2f(A.y), a2 = b2f(A.z), a3 = b2f(A.w);
                s0a = fmaf(a0.x, za.x, s0a); s0b = fmaf(a0.y, za.y, s0b);
                s0a = fmaf(a1.x, za.z, s0a); s0b = fmaf(a1.y, za.w, s0b);
                s0a = fmaf(a2.x, zb.x, s0a); s0b = fmaf(a2.y, zb.y, s0b);
                s0a = fmaf(a3.x, zb.z, s0a); s0b = fmaf(a3.y, zb.w, s0b);
                float2 c0 = b2f(B.x), c1 = b2f(B.y), c2 = b2f(B.z), c3 = b2f(B.w);
                s1a = fmaf(c0.x, za.x, s1a); s1b = fmaf(c0.y, za.y, s1b);
                s1a = fmaf(c1.x, za.z, s1a); s1b = fmaf(c1.y, za.w, s1b);
                s1a = fmaf(c2.x, zb.x, s1a); s1b = fmaf(c2.y, zb.y, s1b);
                s1a = fmaf(c3.x, zb.z, s1a); s1b = fmaf(c3.y, zb.w, s1b);
            }
            float s0 = warpRedSum(s0a + s0b);
            float s1 = warpRedSum(s1a + s1b);
            if (lane == 0) {
                __stcg(&xout[r0], AMASS * rcp(s0 + padterm));
                if (doR1) __stcg(&xout[r0 + 1], AMASS * rcp(s1 + padterm));
            }
        } else if (doPad) {
            float sa = 0.f, sb = 0.f;
#pragma unroll
            for (int k = 0; k < 16; ++k) {
                float4 z = z4[lane + k * 32];
                sa += z.x + z.y; sb += z.z + z.w;
            }
            float s = warpRedSum(sa + sb);
            if (lane == 0) __stcg(odd ? &g_zpad : &g_ypad, AMASS * rcp(s + padterm));
        }

        // ---- grid barrier (R5 mechanism: 1 arrival + 1 spinner per block) ----
        ++phnum;
        __syncthreads();                       // all warps done with zs
        if (tid == 0) {
            __threadfence();                   // publish xout/pad writes
            unsigned int t = atomicAdd(&g_ctr, 1u) + 1u;
            if (t == NBLOCKS * phnum) {
                atomicExch(&g_flag, phnum);    // release
            } else {
                while (__ldcg(&g_flag) < phnum) {}
            }
            __threadfence();                   // acquire before next phase reads
        }
        __syncthreads();
    }
}

// ---- out = 4096 * min(1, y_i * z_j * E_ij) over padded 4096x4096 ----
// Columns >= 2048 are pad: e=1, z=z_pad -> constant per row. Each thread
// emits one computed float4 (left half) + one constant float4 (right half).
__global__ void __launch_bounds__(256) final_kernel(float* __restrict__ out) {
    int i = blockIdx.y;                                  // 0..4095
    int j4 = blockIdx.x * blockDim.x + threadIdx.x;      // 0..511 (left half)

    float zpad = g_zpad;
    float4 o, opad;
    if (i < N0) {
        float y = g_y[i];
        float4 z4 = ((const float4*)g_z)[j4];
        float4 e4 = ((const float4*)g_E)[(size_t)i * (N0 / 4) + j4];
        o.x = SCALE * fminf(1.0f, y * z4.x * e4.x);
        o.y = SCALE * fminf(1.0f, y * z4.y * e4.y);
        o.z = SCALE * fminf(1.0f, y * z4.z * e4.z);
        o.w = SCALE * fminf(1.0f, y * z4.w * e4.w);
        float pv = SCALE * fminf(1.0f, y * zpad);
        opad = make_float4(pv, pv, pv, pv);
    } else {
        float yp = g_ypad;
        float4 z4 = ((const float4*)g_z)[j4];
        o.x = SCALE * fminf(1.0f, yp * z4.x);
        o.y = SCALE * fminf(1.0f, yp * z4.y);
        o.z = SCALE * fminf(1.0f, yp * z4.z);
        o.w = SCALE * fminf(1.0f, yp * z4.w);
        float pv = SCALE * fminf(1.0f, yp * zpad);
        opad = make_float4(pv, pv, pv, pv);
    }
    float4* orow = (float4*)out + (size_t)i * (NPAD / 4);
    __stcs(orow + j4, o);
    __stcs(orow + j4 + 512, opad);
}

extern "C" void kernel_launch(void* const* d_in, const int* in_sizes, int n_in,
                              void* d_out, int out_size) {
    const float* C = (const float*)d_in[0];
    float* out = (float*)d_out;

    prep_kernel<<<dim3(N0 / 32, N0 / 32), dim3(32, 8)>>>(C);
    init_kernel<<<1, 256>>>();
    sinkhorn_persistent<<<NBLOCKS, NT>>>();
    final_kernel<<<dim3(2, NPAD), 256>>>(out);
}